// round 6
// baseline (speedup 1.0000x reference)
#include <cuda_runtime.h>

// ---------------------------------------------------------------------------
// GAT collapses (uniform per-item node features; per-dst softmax weights sum
// to 1 via self-loops) => whole model = 7-layer MLP on 64 batch rows.
// Block-local: 32 blocks x 512 threads, block bx owns rows {2bx, 2bx+1}.
// 16-lane K-split, 2 outputs/warp/pass, double-buffered weight registers
// (software pipeline hides L2 latency), FFMA2 math, acts reg-cached.
// ---------------------------------------------------------------------------

typedef unsigned long long ULL;

__device__ __forceinline__ void ffma2(ULL& d, ULL a, ULL b) {
    asm("fma.rn.f32x2 %0, %1, %2, %0;" : "+l"(d) : "l"(a), "l"(b));
}
__device__ __forceinline__ void fadd2(ULL& d, ULL a) {
    asm("add.rn.f32x2 %0, %1, %0;" : "+l"(d) : "l"(a));
}
__device__ __forceinline__ float2 unpack2f(ULL v) {
    float2 f; asm("mov.b64 {%0, %1}, %2;" : "=f"(f.x), "=f"(f.y) : "l"(v)); return f;
}

// Acts: NQ quads per row for this lane (quad index s + 16*i).
template<int NQ>
__device__ __forceinline__ void load_acts(const float* __restrict__ S0,
                                          const float* __restrict__ S1,
                                          int s, ULL* a0, ULL* a1) {
    #pragma unroll
    for (int i = 0; i < NQ; i++) {
        longlong2 v0 = ((const longlong2*)S0)[s + 16 * i];
        longlong2 v1 = ((const longlong2*)S1)[s + 16 * i];
        a0[2 * i] = (ULL)v0.x; a0[2 * i + 1] = (ULL)v0.y;
        a1[2 * i] = (ULL)v1.x; a1[2 * i + 1] = (ULL)v1.y;
    }
}

// Weights for one pass: this lane's NQ quads of weight row Wrow.
template<int NQ>
__device__ __forceinline__ void loadW(const float* __restrict__ Wrow, int s,
                                      longlong2* wb) {
    const longlong2* wq = (const longlong2*)Wrow;
    #pragma unroll
    for (int i = 0; i < NQ; i++) wb[i] = wq[s + 16 * i];
}

template<int NQ>
__device__ __forceinline__ float2 dotp(const longlong2* wb,
                                       const ULL* a0, const ULL* a1) {
    ULL p0 = 0ull, q0 = 0ull, p1 = 0ull, q1 = 0ull;
    #pragma unroll
    for (int i = 0; i < NQ; i++) {
        ffma2(p0, (ULL)wb[i].x, a0[2 * i]);
        ffma2(q0, (ULL)wb[i].y, a0[2 * i + 1]);
        ffma2(p1, (ULL)wb[i].x, a1[2 * i]);
        ffma2(q1, (ULL)wb[i].y, a1[2 * i + 1]);
    }
    fadd2(p0, q0); fadd2(p1, q1);
    float2 f0 = unpack2f(p0), f1 = unpack2f(p1);
    return make_float2(f0.x + f0.y, f1.x + f1.y);
}

// Reduce over 16 lanes (bits 0..3), lane s==0 writes relu(v+bias).
__device__ __forceinline__ void redstore(float2 v, float bias, int s,
                                         float* __restrict__ O0,
                                         float* __restrict__ O1, int o) {
    #pragma unroll
    for (int m = 1; m <= 8; m <<= 1) {
        v.x += __shfl_xor_sync(0xffffffffu, v.x, m);
        v.y += __shfl_xor_sync(0xffffffffu, v.y, m);
    }
    if (s == 0) {
        O0[o] = fmaxf(v.x + bias, 0.f);
        O1[o] = fmaxf(v.y + bias, 0.f);
    }
}

// Pipelined layer: NP passes x 2 outputs; weight rows selected by getW(p).
// getW: (pass) -> pointer to this thread's weight row base; getB: bias.
template<int NQ, int NP, typename FW, typename FB>
__device__ __forceinline__ void layer_pipe(FW getW, FB getB, int K,
                                           const float* __restrict__ S0,
                                           const float* __restrict__ S1,
                                           float* __restrict__ O0,
                                           float* __restrict__ O1,
                                           int s, typename
                                           /*dummy*/ std::nullptr_t = nullptr) {
    ULL a0[2 * NQ], a1[2 * NQ];
    load_acts<NQ>(S0, S1, s, a0, a1);
    longlong2 wb[2][NQ];
    loadW<NQ>(getW(0), s, wb[0]);
    #pragma unroll
    for (int p = 0; p < NP; p++) {
        if (p + 1 < NP) loadW<NQ>(getW(p + 1), s, wb[(p + 1) & 1]);
        float2 v = dotp<NQ>(wb[p & 1], a0, a1);
        redstore(v, getB(p), s, O0, O1, /*o=*/0), (void)0;
    }
}

__global__ __launch_bounds__(512, 1) void net_kernel(
    const float* __restrict__ x, const int* __restrict__ cidx,
    const float* __restrict__ W_in, const float* __restrict__ b_in,
    const float* __restrict__ gat_W, const float* __restrict__ gat_b,
    const float* __restrict__ emb,
    const float* __restrict__ W_fuse, const float* __restrict__ b_fuse,
    const float* __restrict__ W_p1, const float* __restrict__ b_p1,
    const float* __restrict__ W_p2, const float* __restrict__ b_p2,
    const float* __restrict__ W_p3, const float* __restrict__ b_p3,
    const float* __restrict__ W_d1, const float* __restrict__ b_d1,
    const float* __restrict__ W_d2, const float* __restrict__ b_d2,
    const float* __restrict__ W_d3, const float* __restrict__ b_d3,
    float* __restrict__ out) {

    __shared__ __align__(16) float X[2][64];
    __shared__ __align__(16) float A[2][336];
    __shared__ __align__(16) float B[2][336];
    __shared__ __align__(16) float C[2][128];

    const int t    = threadIdx.x;
    const int bx   = blockIdx.x;
    const int lane = t & 31;
    const int w    = t >> 5;       // warp 0..15
    const int s    = lane & 15;    // K-slice within 16-lane group
    const int grp  = lane >> 4;    // output-within-pass 0..1

    // ---- stage inputs: x rows -> X; emb[cidx] -> B[r][256..319] ----
    if (t < 32) {
        int r = t >> 4, q = t & 15;
        ((float4*)X[r])[q] = ((const float4*)x)[(2 * bx + r) * 16 + q];
    } else if (t < 64) {
        int i = t - 32, r = i >> 4, q = i & 15;
        int ci = cidx[2 * bx + r];
        ((float4*)(B[r] + 256))[q] = ((const float4*)emb)[ci * 16 + q];
    }
    __syncthreads();

    // ================= L0: [256 x 64], X -> A (NQ=1, 8 passes) =============
    {
        ULL a0[2], a1[2];
        load_acts<1>(X[0], X[1], s, a0, a1);
        longlong2 wb[2][1];
        int o0 = w * 16 + grp;
        loadW<1>(W_in + o0 * 64, s, wb[0]);
        #pragma unroll
        for (int p = 0; p < 8; p++) {
            int onx = w * 16 + (p + 1) * 2 + grp;
            if (p < 7) loadW<1>(W_in + onx * 64, s, wb[(p + 1) & 1]);
            int o = w * 16 + p * 2 + grp;
            float2 v = dotp<1>(wb[p & 1], a0, a1);
            redstore(v, b_in[o], s, A[0], A[1], o);
        }
    }
    __syncthreads();

    // ============ L1-L3: collapsed GAT [256 x 256] (NQ=4, 8 passes) =========
    #pragma unroll 1
    for (int l = 0; l < 3; l++) {
        const float* W = gat_W + l * 65536;
        const float* bb = gat_b + l * 256;
        const float* S0 = (l & 1) ? B[0] : A[0];
        const float* S1 = (l & 1) ? B[1] : A[1];
        float* O0 = (l & 1) ? A[0] : B[0];
        float* O1 = (l & 1) ? A[1] : B[1];
        ULL a0[8], a1[8];
        load_acts<4>(S0, S1, s, a0, a1);
        longlong2 wb[2][4];
        loadW<4>(W + (w * 16 + grp) * 256, s, wb[0]);
        #pragma unroll
        for (int p = 0; p < 8; p++) {
            if (p < 7) loadW<4>(W + (w * 16 + (p + 1) * 2 + grp) * 256, s, wb[(p + 1) & 1]);
            int o = w * 16 + p * 2 + grp;
            float2 v = dotp<4>(wb[p & 1], a0, a1);
            redstore(v, bb[o], s, O0, O1, o);
        }
        __syncthreads();
    }

    // ========== L4: fuse [256 x 320] over [g3 ; emb], B -> A (NQ=5) =========
    {
        ULL a0[10], a1[10];
        load_acts<5>(B[0], B[1], s, a0, a1);
        longlong2 wb[2][5];
        loadW<5>(W_fuse + (w * 16 + grp) * 320, s, wb[0]);
        #pragma unroll
        for (int p = 0; p < 8; p++) {
            if (p < 7) loadW<5>(W_fuse + (w * 16 + (p + 1) * 2 + grp) * 320, s, wb[(p + 1) & 1]);
            int o = w * 16 + p * 2 + grp;
            float2 v = dotp<5>(wb[p & 1], a0, a1);
            redstore(v, b_fuse[o], s, A[0], A[1], o);
        }
    }
    __syncthreads();

    // ========= L5: heads stage1 [p1 ; d1] = [256 x 256], A -> B (NQ=4) ======
    {
        ULL a0[8], a1[8];
        load_acts<4>(A[0], A[1], s, a0, a1);
        // o<128 -> p1 row o, else d1 row o-128
        auto wrow = [&](int o) {
            return (o < 128) ? (W_p1 + o * 256) : (W_d1 + (o - 128) * 256);
        };
        longlong2 wb[2][4];
        loadW<4>(wrow(w * 16 + grp), s, wb[0]);
        #pragma unroll
        for (int p = 0; p < 8; p++) {
            if (p < 7) loadW<4>(wrow(w * 16 + (p + 1) * 2 + grp), s, wb[(p + 1) & 1]);
            int o = w * 16 + p * 2 + grp;
            float b5 = (o < 128) ? b_p1[o] : b_d1[o - 128];
            float2 v = dotp<4>(wb[p & 1], a0, a1);
            redstore(v, b5, s, B[0], B[1], o);
        }
    }
    __syncthreads();

    // == L6: p2 (warps 0-7) / d2 (warps 8-15), [64 x 128], B -> C (NQ=2) =====
    {
        const bool is_d = (w >= 8);
        const int hb = is_d ? 128 : 0;
        const int wl = w & 7;                    // warp-local 0..7
        const float* W2 = is_d ? W_d2 : W_p2;
        const float* b2 = is_d ? b_d2 : b_p2;
        ULL a0[4], a1[4];
        load_acts<2>(B[0] + hb, B[1] + hb, s, a0, a1);
        longlong2 wb[2][2];
        loadW<2>(W2 + (wl * 8 + grp) * 128, s, wb[0]);
        #pragma unroll
        for (int p = 0; p < 4; p++) {
            if (p < 3) loadW<2>(W2 + (wl * 8 + (p + 1) * 2 + grp) * 128, s, wb[(p + 1) & 1]);
            int ol = wl * 8 + p * 2 + grp;       // 0..63 local
            float2 v = dotp<2>(wb[p & 1], a0, a1);
            redstore(v, b2[ol], s, C[0], C[1], ol + (is_d ? 64 : 0));
        }
    }
    __syncthreads();

    // ==== L7: final 64-dots; warps 0-3 = {r0 price, r0 dir, r1 price, r1 dir}
    if (w < 4) {
        const int r = w >> 1, is_d = w & 1;
        const float* W3 = is_d ? W_d3 : W_p3;
        const float* Cv = C[r] + is_d * 64;
        float v = W3[lane] * Cv[lane] + W3[lane + 32] * Cv[lane + 32];
        #pragma unroll
        for (int m = 16; m; m >>= 1)
            v += __shfl_xor_sync(0xffffffffu, v, m);
        if (lane == 0) {
            int rg = 2 * bx + r;
            if (!is_d) out[rg] = v + b_p3[0];
            else       out[64 + rg] = 1.f / (1.f + __expf(-(v + b_d3[0])));
        }
    }
}

extern "C" void kernel_launch(void* const* d_in, const int* in_sizes, int n_in,
                              void* d_out, int out_size) {
    const float* x      = (const float*)d_in[0];
    const int*   cidx   = (const int*)  d_in[1];
    // d_in[2] edge_index, d_in[3] edge_attr: unused (softmax collapse)
    const float* W_in   = (const float*)d_in[4];
    const float* b_in   = (const float*)d_in[5];
    const float* gat_W  = (const float*)d_in[6];
    // d_in[7..10]: attention params — unused (collapse)
    const float* gat_b  = (const float*)d_in[11];
    const float* emb    = (const float*)d_in[12];
    const float* W_fuse = (const float*)d_in[13];
    const float* b_fuse = (const float*)d_in[14];
    const float* W_p1   = (const float*)d_in[15];
    const float* b_p1   = (const float*)d_in[16];
    const float* W_p2   = (const float*)d_in[17];
    const float* b_p2   = (const float*)d_in[18];
    const float* W_p3   = (const float*)d_in[19];
    const float* b_p3   = (const float*)d_in[20];
    const float* W_d1   = (const float*)d_in[21];
    const float* b_d1   = (const float*)d_in[22];
    const float* W_d2   = (const float*)d_in[23];
    const float* b_d2   = (const float*)d_in[24];
    const float* W_d3   = (const float*)d_in[25];
    const float* b_d3   = (const float*)d_in[26];

    net_kernel<<<32, 512>>>(x, cidx, W_in, b_in, gat_W, gat_b, emb,
                            W_fuse, b_fuse, W_p1, b_p1, W_p2, b_p2,
                            W_p3, b_p3, W_d1, b_d1, W_d2, b_d2,
                            W_d3, b_d3, (float*)d_out);
}